// round 4
// baseline (speedup 1.0000x reference)
#include <cuda_runtime.h>
#include <cuda_bf16.h>

#define M 512
#define T 512                 // threads per primitive: 1 node per thread
#define NWP (T / 32)          // 16 warps
#define FULL 0xffffffffu
#define EPS_F 1e-12f
#define DEAD 0xffffffffu      // sentinel bits for visited nodes (max uint)

__device__ float    g_mean_scratch[4096];
__device__ unsigned g_done_count = 0;

__global__ void __launch_bounds__(T, 2) prim_mst(
    const float* __restrict__ xyz,
    const float* __restrict__ alpha_p,
    float* __restrict__ out,
    int P, int n, int B, int nprim)
{
    __shared__ float sx[M], sy[M], sz[M];
    __shared__ alignas(16) unsigned long long s_pack[2][NWP];  // double-buffered per-warp winners
    __shared__ float s_red[NWP];
    __shared__ unsigned s_old;

    const int tid  = threadIdx.x;
    const int lane = tid & 31;
    const int warp = tid >> 5;
    const int bp   = blockIdx.x;                    // primitive id
    const float* src = xyz + (size_t)bp * (3 * M);

    // One-time coalesced load + deinterleave into SoA shared.
    for (int i = tid; i < 3 * M; i += T) {
        float v = __ldg(src + i);
        int row = i / 3, c = i - 3 * row;
        if (c == 0)      sx[row] = v;
        else if (c == 1) sy[row] = v;
        else             sz[row] = v;
    }
    __syncthreads();

    // Thread tid owns node tid.
    const float px = sx[tid], py = sy[tid], pz = sz[tid];

    // Init: best_d = distance to node 0. Exact reference arithmetic throughout:
    // no FMA contraction (__f*_rn), fmaxf(s, EPS), IEEE __fsqrt_rn, strict <.
    const float x0 = sx[0], y0 = sy[0], z0 = sz[0];
    float dx = __fsub_rn(px, x0);
    float dy = __fsub_rn(py, y0);
    float dz = __fsub_rn(pz, z0);
    float s  = __fadd_rn(__fadd_rn(__fmul_rn(dx, dx), __fmul_rn(dy, dy)), __fmul_rn(dz, dz));
    s = fmaxf(s, EPS_F);
    unsigned mv = __float_as_uint(__fsqrt_rn(s));   // uint order == float order (positives)
    int   bpar = 0;                                 // best_p init = 0 (matches reference)
    float cost = 0.0f;
    if (tid == 0) { mv = DEAD; bpar = -1; }         // node 0 = root, visited

    // ---- Prim: 511 sequential selections, ONE barrier per iteration ----
    for (int it = 0; it < M - 1; ++it) {
        // Stage 1: warp argmin. Value REDUX, then min-index REDUX among value-ties
        // (tid order == node order -> first occurrence).
        const unsigned vb   = mv;
        const unsigned g    = __reduce_min_sync(FULL, vb);
        const unsigned cand = (vb == g) ? (unsigned)tid : 0xffffffffu;
        const unsigned widx = __reduce_min_sync(FULL, cand);
        unsigned long long* pk_buf = s_pack[it & 1];
        if (lane == 0)
            pk_buf[warp] = ((unsigned long long)g << 32) | widx;
        __syncthreads();

        // Stage 2: every thread redundantly min-reduces the 16 packed winners
        // (4x LDS.128 broadcast + depth-4 tree). No second barrier needed.
        const ulonglong2* pv = (const ulonglong2*)pk_buf;
        ulonglong2 a0 = pv[0], a1 = pv[1], a2 = pv[2], a3 = pv[3];
        ulonglong2 b0 = pv[4], b1 = pv[5], b2 = pv[6], b3 = pv[7];
        unsigned long long m0 = min(a0.x, a0.y), m1 = min(a1.x, a1.y);
        unsigned long long m2 = min(a2.x, a2.y), m3 = min(a3.x, a3.y);
        unsigned long long m4 = min(b0.x, b0.y), m5 = min(b1.x, b1.y);
        unsigned long long m6 = min(b2.x, b2.y), m7 = min(b3.x, b3.y);
        m0 = min(m0, m1); m2 = min(m2, m3); m4 = min(m4, m5); m6 = min(m6, m7);
        m0 = min(m0, m2); m4 = min(m4, m6);
        const unsigned long long pk = min(m0, m4);

        const int      u    = (int)(unsigned)pk;
        const unsigned uval = (unsigned)(pk >> 32);

        // Relax own node against u (exact reference arithmetic).
        const float ux = sx[u], uy = sy[u], uz = sz[u];
        dx = __fsub_rn(px, ux);
        dy = __fsub_rn(py, uy);
        dz = __fsub_rn(pz, uz);
        s  = __fadd_rn(__fadd_rn(__fmul_rn(dx, dx), __fmul_rn(dy, dy)), __fmul_rn(dz, dz));
        s = fmaxf(s, EPS_F);
        const unsigned db = __float_as_uint(__fsqrt_rn(s));
        const bool isu = (tid == u);
        const bool upd = (mv != DEAD) && !isu && (db < mv);
        if (upd) { mv = db; bpar = u; }
        if (isu) { mv = DEAD; cost = __uint_as_float(uval); }  // selection freezes cost+parent
    }

    // ---- Mean MST edge length over the primitive ----
    float sum = cost;
    #pragma unroll
    for (int off = 16; off; off >>= 1) sum += __shfl_xor_sync(FULL, sum, off);
    if (lane == 0) s_red[warp] = sum;
    __syncthreads();
    float tot = s_red[0];
    #pragma unroll
    for (int q = 1; q < NWP; ++q) tot += s_red[q];
    const float mean  = tot / (float)(M - 1);
    const float alpha = *alpha_p;
    const float thr   = alpha * mean;

    // ---- Outputs ----
    const int b     = bp / P;
    const int pl    = bp - b * P;
    const int gbase = pl * M;
    const size_t go = (size_t)b * n + gbase + tid;

    const bool mk = cost > thr;
    out[go]                 = mk ? cost : 0.0f;                     // dist
    out[(size_t)B * n + go] = mk ? (float)(bpar + gbase) : -1.0f;   // assign (float-cast)

    // ---- Fused per-cloud mean-of-means: last-block-done pattern ----
    if (tid == 0) g_mean_scratch[bp] = mean;
    __threadfence();
    if (tid == 0) s_old = atomicAdd(&g_done_count, 1u);
    __syncthreads();
    if (s_old == (unsigned)(nprim - 1)) {
        __threadfence();
        for (int b2 = tid; b2 < B; b2 += T) {
            float s2 = 0.0f;
            for (int p = 0; p < P; ++p) s2 += g_mean_scratch[b2 * P + p];
            out[(size_t)2 * B * n + b2] = s2 / (float)P;
        }
        if (tid == 0) g_done_count = 0;   // reset for next graph replay
    }
}

extern "C" void kernel_launch(void* const* d_in, const int* in_sizes, int n_in,
                              void* d_out, int out_size)
{
    const float* xyz   = (const float*)d_in[0];
    // d_in[1] = primitive_size (512, compile-time M)
    const float* alpha = (const float*)d_in[2];

    const int Bn = in_sizes[0] / 3;     // B*n
    const int B  = out_size - 2 * Bn;   // out = 2*B*n + B floats
    const int n  = Bn / B;
    const int P  = n / M;
    const int nprim = B * P;

    prim_mst<<<nprim, T>>>(xyz, alpha, (float*)d_out, P, n, B, nprim);
}

// round 6
// speedup vs baseline: 1.6232x; 1.6232x over previous
#include <cuda_runtime.h>
#include <cuda_bf16.h>

#define M 512
#define T 512                 // threads per primitive: 1 node per thread
#define NWP (T / 32)          // 16 warps
#define FULL 0xffffffffu
#define EPS_F 1e-12f
#define DEAD 0xffffffffu      // sentinel bits for visited nodes (max uint)

__device__ float    g_mean_scratch[4096];
__device__ unsigned g_done_count = 0;

__global__ void __launch_bounds__(T, 2) prim_mst(
    const float* __restrict__ xyz,
    const float* __restrict__ alpha_p,
    float* __restrict__ out,
    int P, int n, int B, int nprim)
{
    __shared__ float4 sp[M];                              // node coords (w unused)
    __shared__ alignas(16) unsigned long long s_min[4];   // rotating argmin slots
    __shared__ float s_red[NWP];
    __shared__ unsigned s_old;

    const int tid  = threadIdx.x;
    const int lane = tid & 31;
    const int warp = tid >> 5;
    const int bp   = blockIdx.x;                    // primitive id
    const float* src = xyz + (size_t)bp * (3 * M);

    // Load own node coords + publish to shared as float4 (one LDS.128 broadcast later).
    const float px = __ldg(src + 3 * tid + 0);
    const float py = __ldg(src + 3 * tid + 1);
    const float pz = __ldg(src + 3 * tid + 2);
    sp[tid] = make_float4(px, py, pz, 0.0f);
    if (tid < 4) s_min[tid] = ~0ULL;
    __syncthreads();

    // Init: best_d = distance to node 0. Exact reference arithmetic throughout:
    // no FMA contraction (__f*_rn), fmaxf(s, EPS), IEEE __fsqrt_rn, strict <.
    const float4 p0 = sp[0];
    float dx = __fsub_rn(px, p0.x);
    float dy = __fsub_rn(py, p0.y);
    float dz = __fsub_rn(pz, p0.z);
    float s  = __fadd_rn(__fadd_rn(__fmul_rn(dx, dx), __fmul_rn(dy, dy)), __fmul_rn(dz, dz));
    s = fmaxf(s, EPS_F);
    unsigned mv = __float_as_uint(__fsqrt_rn(s));   // uint order == float order (positives)
    int   bpar = 0;                                 // best_p init = 0 (matches reference)
    float cost = 0.0f;
    if (tid == 0) { mv = DEAD; bpar = -1; }         // node 0 = root, visited

    // ---- Prim: 511 sequential selections, ONE barrier per iteration ----
    for (int it = 0; it < M - 1; ++it) {
        // Warp value-min; lanes holding the (alive) warp min race via packed
        // atomicMin: (value<<32 | tid). u64 min == (min value, then min tid)
        // == first-occurrence tie-break, identical to jnp.argmin.
        const unsigned g = __reduce_min_sync(FULL, mv);
        unsigned long long* slot = &s_min[it & 3];
        if (mv == g && g != DEAD)
            atomicMin_block(slot, ((unsigned long long)g << 32) | (unsigned)tid);
        // Rotate: reset the slot used two iterations ahead. Its last readers
        // finished before bar(it-1); its next writers start after bar(it). Safe.
        if (tid == T - 1) s_min[(it + 2) & 3] = ~0ULL;
        __syncthreads();

        const unsigned long long pk = *slot;
        const int      u    = (int)(unsigned)pk;
        const unsigned uval = (unsigned)(pk >> 32);

        // Relax own node against u (exact reference arithmetic).
        const float4 up = sp[u];                     // broadcast LDS.128
        dx = __fsub_rn(px, up.x);
        dy = __fsub_rn(py, up.y);
        dz = __fsub_rn(pz, up.z);
        s  = __fadd_rn(__fadd_rn(__fmul_rn(dx, dx), __fmul_rn(dy, dy)), __fmul_rn(dz, dz));
        s = fmaxf(s, EPS_F);
        const unsigned db = __float_as_uint(__fsqrt_rn(s));
        const bool isu = (tid == u);
        const bool upd = (mv != DEAD) && !isu && (db < mv);
        if (upd) { mv = db; bpar = u; }
        if (isu) { mv = DEAD; cost = __uint_as_float(uval); }  // selection freezes cost+parent
    }

    // ---- Mean MST edge length over the primitive ----
    float sum = cost;
    #pragma unroll
    for (int off = 16; off; off >>= 1) sum += __shfl_xor_sync(FULL, sum, off);
    if (lane == 0) s_red[warp] = sum;
    __syncthreads();
    float tot = s_red[0];
    #pragma unroll
    for (int q = 1; q < NWP; ++q) tot += s_red[q];
    const float mean  = tot / (float)(M - 1);
    const float alpha = *alpha_p;
    const float thr   = alpha * mean;

    // ---- Outputs ----
    const int b     = bp / P;
    const int pl    = bp - b * P;
    const int gbase = pl * M;
    const size_t go = (size_t)b * n + gbase + tid;

    const bool mk = cost > thr;
    out[go]                 = mk ? cost : 0.0f;                     // dist
    out[(size_t)B * n + go] = mk ? (float)(bpar + gbase) : -1.0f;   // assign (float-cast)

    // ---- Fused per-cloud mean-of-means: last-block-done pattern ----
    if (tid == 0) g_mean_scratch[bp] = mean;
    __threadfence();
    if (tid == 0) s_old = atomicAdd(&g_done_count, 1u);
    __syncthreads();
    if (s_old == (unsigned)(nprim - 1)) {
        __threadfence();
        for (int b2 = tid; b2 < B; b2 += T) {
            float s2 = 0.0f;
            for (int p = 0; p < P; ++p) s2 += g_mean_scratch[b2 * P + p];
            out[(size_t)2 * B * n + b2] = s2 / (float)P;
        }
        if (tid == 0) g_done_count = 0;   // reset for next graph replay
    }
}

extern "C" void kernel_launch(void* const* d_in, const int* in_sizes, int n_in,
                              void* d_out, int out_size)
{
    const float* xyz   = (const float*)d_in[0];
    // d_in[1] = primitive_size (512, compile-time M)
    const float* alpha = (const float*)d_in[2];

    const int Bn = in_sizes[0] / 3;     // B*n
    const int B  = out_size - 2 * Bn;   // out = 2*B*n + B floats
    const int n  = Bn / B;
    const int P  = n / M;
    const int nprim = B * P;

    prim_mst<<<nprim, T>>>(xyz, alpha, (float*)d_out, P, n, B, nprim);
}

// round 7
// speedup vs baseline: 2.4764x; 1.5256x over previous
#include <cuda_runtime.h>
#include <cuda_bf16.h>

#define M 512
#define T 512                 // threads per primitive: 1 node per thread
#define NWP (T / 32)          // 16 warps
#define FULL 0xffffffffu
#define EPS_F 1e-12f
#define DEAD 0xffffffffu      // sentinel bits for visited nodes (max uint)

__device__ float    g_mean_scratch[4096];
__device__ unsigned g_done_count = 0;

__global__ void __launch_bounds__(T, 2) prim_mst(
    const float* __restrict__ xyz,
    const float* __restrict__ alpha_p,
    float* __restrict__ out,
    int P, int n, int B, int nprim)
{
    __shared__ float4 sp[M];                                   // node coords (w unused)
    __shared__ alignas(16) unsigned long long s_pack[2][NWP];  // double-buffered warp winners
    __shared__ float s_red[NWP];
    __shared__ unsigned s_old;

    const int tid  = threadIdx.x;
    const int lane = tid & 31;
    const int warp = tid >> 5;
    const int bp   = blockIdx.x;                    // primitive id
    const float* src = xyz + (size_t)bp * (3 * M);

    // Load own node coords + publish as float4 (single LDS.128 broadcast later).
    const float px = __ldg(src + 3 * tid + 0);
    const float py = __ldg(src + 3 * tid + 1);
    const float pz = __ldg(src + 3 * tid + 2);
    sp[tid] = make_float4(px, py, pz, 0.0f);
    __syncthreads();

    // Init: best_d = distance to node 0. Exact reference arithmetic throughout:
    // no FMA contraction (__f*_rn), fmaxf(s, EPS), IEEE __fsqrt_rn, strict <.
    const float4 p0 = sp[0];
    float dx = __fsub_rn(px, p0.x);
    float dy = __fsub_rn(py, p0.y);
    float dz = __fsub_rn(pz, p0.z);
    float s  = __fadd_rn(__fadd_rn(__fmul_rn(dx, dx), __fmul_rn(dy, dy)), __fmul_rn(dz, dz));
    s = fmaxf(s, EPS_F);
    unsigned mv = __float_as_uint(__fsqrt_rn(s));   // uint order == float order (positives)
    int   bpar = 0;                                 // best_p init = 0 (matches reference)
    float cost = 0.0f;
    if (tid == 0) { mv = DEAD; bpar = -1; }         // node 0 = root, visited

    // ---- Prim: 511 sequential selections, ONE barrier per iteration ----
    for (int it = 0; it < M - 1; ++it) {
        // Stage 1: warp value-min (REDUX), winner tid via ballot+ffs
        // (lowest lane among value ties == first occurrence, tid order == node order).
        const unsigned g    = __reduce_min_sync(FULL, mv);
        const unsigned ball = __ballot_sync(FULL, mv == g);
        const unsigned widx = (unsigned)(warp * 32) + (unsigned)(__ffs(ball) - 1);
        if (lane == 0)
            s_pack[it & 1][warp] = ((unsigned long long)g << 32) | widx;
        __syncthreads();

        // Stage 2: every warp redundantly reduces the 16 packed winners via REDUX.
        // No second barrier, no extra round-trip: u and its cost land in all lanes.
        unsigned v  = 0xffffffffu, ii = 0xffffffffu;
        if (lane < NWP) {
            const unsigned long long pk = s_pack[it & 1][lane];
            v  = (unsigned)(pk >> 32);
            ii = (unsigned)pk;
        }
        const unsigned g2   = __reduce_min_sync(FULL, v);
        const unsigned cand = (v == g2) ? ii : 0xffffffffu;
        const unsigned u    = __reduce_min_sync(FULL, cand);   // min tid among value ties
        const unsigned uval = g2;

        // Relax own node against u (exact reference arithmetic).
        const float4 up = sp[u];                     // broadcast LDS.128
        dx = __fsub_rn(px, up.x);
        dy = __fsub_rn(py, up.y);
        dz = __fsub_rn(pz, up.z);
        s  = __fadd_rn(__fadd_rn(__fmul_rn(dx, dx), __fmul_rn(dy, dy)), __fmul_rn(dz, dz));
        s = fmaxf(s, EPS_F);
        const unsigned db = __float_as_uint(__fsqrt_rn(s));
        const bool isu = ((unsigned)tid == u);
        const bool upd = (mv != DEAD) && !isu && (db < mv);
        if (upd) { mv = db; bpar = (int)u; }
        if (isu) { mv = DEAD; cost = __uint_as_float(uval); }  // selection freezes cost+parent
    }

    // ---- Mean MST edge length over the primitive ----
    float sum = cost;
    #pragma unroll
    for (int off = 16; off; off >>= 1) sum += __shfl_xor_sync(FULL, sum, off);
    if (lane == 0) s_red[warp] = sum;
    __syncthreads();
    float tot = s_red[0];
    #pragma unroll
    for (int q = 1; q < NWP; ++q) tot += s_red[q];
    const float mean  = tot / (float)(M - 1);
    const float alpha = *alpha_p;
    const float thr   = alpha * mean;

    // ---- Outputs ----
    const int b     = bp / P;
    const int pl    = bp - b * P;
    const int gbase = pl * M;
    const size_t go = (size_t)b * n + gbase + tid;

    const bool mk = cost > thr;
    out[go]                 = mk ? cost : 0.0f;                     // dist
    out[(size_t)B * n + go] = mk ? (float)(bpar + gbase) : -1.0f;   // assign (float-cast)

    // ---- Fused per-cloud mean-of-means: last-block-done pattern ----
    if (tid == 0) g_mean_scratch[bp] = mean;
    __threadfence();
    if (tid == 0) s_old = atomicAdd(&g_done_count, 1u);
    __syncthreads();
    if (s_old == (unsigned)(nprim - 1)) {
        __threadfence();
        for (int b2 = tid; b2 < B; b2 += T) {
            float s2 = 0.0f;
            for (int p = 0; p < P; ++p) s2 += g_mean_scratch[b2 * P + p];
            out[(size_t)2 * B * n + b2] = s2 / (float)P;
        }
        if (tid == 0) g_done_count = 0;   // reset for next graph replay
    }
}

extern "C" void kernel_launch(void* const* d_in, const int* in_sizes, int n_in,
                              void* d_out, int out_size)
{
    const float* xyz   = (const float*)d_in[0];
    // d_in[1] = primitive_size (512, compile-time M)
    const float* alpha = (const float*)d_in[2];

    const int Bn = in_sizes[0] / 3;     // B*n
    const int B  = out_size - 2 * Bn;   // out = 2*B*n + B floats
    const int n  = Bn / B;
    const int P  = n / M;
    const int nprim = B * P;

    prim_mst<<<nprim, T>>>(xyz, alpha, (float*)d_out, P, n, B, nprim);
}

// round 8
// speedup vs baseline: 2.9055x; 1.1733x over previous
#include <cuda_runtime.h>
#include <cuda_bf16.h>

#define M 512
#define T 256                 // threads per primitive: 2 nodes per thread
#define NWP (T / 32)          // 8 warps
#define FULL 0xffffffffu
#define EPS_F 1e-12f
#define DEAD 0xffffffffu      // sentinel bits for visited nodes (max uint)

__device__ float    g_mean_scratch[4096];
__device__ unsigned g_done_count = 0;

__global__ void __launch_bounds__(T, 2) prim_mst(
    const float* __restrict__ xyz,
    const float* __restrict__ alpha_p,
    float* __restrict__ out,
    int P, int n, int B, int nprim)
{
    __shared__ float4 sp[M];                                   // node coords (w unused)
    __shared__ alignas(16) unsigned long long s_pack[2][NWP];  // double-buffered warp winners
    __shared__ float s_red[NWP];
    __shared__ unsigned s_old;

    const int tid  = threadIdx.x;
    const int lane = tid & 31;
    const int warp = tid >> 5;
    const int bp   = blockIdx.x;                    // primitive id
    const float* src = xyz + (size_t)bp * (3 * M);

    // Blocked ownership: thread owns nodes id0=2*tid, id1=2*tid+1
    // (lane order == node order -> ballot/REDUX tie-breaks give first occurrence).
    const int id0 = 2 * tid, id1 = 2 * tid + 1;

    // Coalesced load + publish coords as float4 (single LDS.128 broadcast later).
    {
        const float a0 = __ldg(src + 6 * tid + 0);
        const float a1 = __ldg(src + 6 * tid + 1);
        const float a2 = __ldg(src + 6 * tid + 2);
        const float a3 = __ldg(src + 6 * tid + 3);
        const float a4 = __ldg(src + 6 * tid + 4);
        const float a5 = __ldg(src + 6 * tid + 5);
        sp[id0] = make_float4(a0, a1, a2, 0.0f);
        sp[id1] = make_float4(a3, a4, a5, 0.0f);
    }
    __syncthreads();

    const float4 P0c = sp[id0], P1c = sp[id1];
    const float4 p0  = sp[0];

    // Init: best_d = distance to node 0. Exact reference arithmetic throughout:
    // no FMA contraction (__f*_rn), fmaxf(s, EPS), IEEE __fsqrt_rn, strict <.
    unsigned mv0, mv1;
    {
        float dx = __fsub_rn(P0c.x, p0.x), dy = __fsub_rn(P0c.y, p0.y), dz = __fsub_rn(P0c.z, p0.z);
        float s  = __fadd_rn(__fadd_rn(__fmul_rn(dx, dx), __fmul_rn(dy, dy)), __fmul_rn(dz, dz));
        mv0 = __float_as_uint(__fsqrt_rn(fmaxf(s, EPS_F)));
        dx = __fsub_rn(P1c.x, p0.x); dy = __fsub_rn(P1c.y, p0.y); dz = __fsub_rn(P1c.z, p0.z);
        s  = __fadd_rn(__fadd_rn(__fmul_rn(dx, dx), __fmul_rn(dy, dy)), __fmul_rn(dz, dz));
        mv1 = __float_as_uint(__fsqrt_rn(fmaxf(s, EPS_F)));
    }
    int   bpar0 = 0, bpar1 = 0;     // best_p init = 0 (matches reference)
    float cost0 = 0.0f, cost1 = 0.0f;
    if (tid == 0) { mv0 = DEAD; bpar0 = -1; }   // node 0 = root, visited

    // ---- Prim: 511 sequential selections, ONE barrier per iteration ----
    for (int it = 0; it < M - 1; ++it) {
        // Local 2-way argmin (strict < : tie -> slot0 == lower node id).
        const bool sel1     = (mv1 < mv0);
        const unsigned lval = sel1 ? mv1 : mv0;
        const unsigned lidx = sel1 ? (unsigned)id1 : (unsigned)id0;

        // Warp argmin: value REDUX, then min node id among value ties.
        const unsigned g    = __reduce_min_sync(FULL, lval);
        const unsigned cand = (lval == g) ? lidx : 0xffffffffu;
        const unsigned wi   = __reduce_min_sync(FULL, cand);
        if (lane == 0)
            s_pack[it & 1][warp] = ((unsigned long long)g << 32) | wi;
        __syncthreads();

        // Stage 2: all warps redundantly reduce the 8 packed winners via REDUX.
        // lane&7 -> duplicates don't affect min; no predicate/fill needed.
        const unsigned long long pk = s_pack[it & 1][lane & 7];
        const unsigned v  = (unsigned)(pk >> 32);
        const unsigned ii = (unsigned)pk;
        const unsigned g2 = __reduce_min_sync(FULL, v);
        const unsigned c2 = (v == g2) ? ii : 0xffffffffu;
        const unsigned u  = __reduce_min_sync(FULL, c2);   // min id among value ties
        const unsigned uval = g2;

        // Relax both owned nodes against u (exact reference arithmetic).
        const float4 up = sp[u];                     // broadcast LDS.128
        {
            float dx = __fsub_rn(P0c.x, up.x), dy = __fsub_rn(P0c.y, up.y), dz = __fsub_rn(P0c.z, up.z);
            float s  = __fadd_rn(__fadd_rn(__fmul_rn(dx, dx), __fmul_rn(dy, dy)), __fmul_rn(dz, dz));
            const unsigned db = __float_as_uint(__fsqrt_rn(fmaxf(s, EPS_F)));
            const bool isu = ((unsigned)id0 == u);
            const bool upd = (mv0 != DEAD) && !isu && (db < mv0);
            if (upd) { mv0 = db; bpar0 = (int)u; }
            if (isu) { mv0 = DEAD; cost0 = __uint_as_float(uval); }
        }
        {
            float dx = __fsub_rn(P1c.x, up.x), dy = __fsub_rn(P1c.y, up.y), dz = __fsub_rn(P1c.z, up.z);
            float s  = __fadd_rn(__fadd_rn(__fmul_rn(dx, dx), __fmul_rn(dy, dy)), __fmul_rn(dz, dz));
            const unsigned db = __float_as_uint(__fsqrt_rn(fmaxf(s, EPS_F)));
            const bool isu = ((unsigned)id1 == u);
            const bool upd = (mv1 != DEAD) && !isu && (db < mv1);
            if (upd) { mv1 = db; bpar1 = (int)u; }
            if (isu) { mv1 = DEAD; cost1 = __uint_as_float(uval); }
        }
    }

    // ---- Mean MST edge length over the primitive ----
    float sum = cost0 + cost1;
    #pragma unroll
    for (int off = 16; off; off >>= 1) sum += __shfl_xor_sync(FULL, sum, off);
    if (lane == 0) s_red[warp] = sum;
    __syncthreads();
    float tot = s_red[0];
    #pragma unroll
    for (int q = 1; q < NWP; ++q) tot += s_red[q];
    const float mean  = tot / (float)(M - 1);
    const float alpha = *alpha_p;
    const float thr   = alpha * mean;

    // ---- Outputs (float2 per array) ----
    const int b     = bp / P;
    const int pl    = bp - b * P;
    const int gbase = pl * M;
    const size_t go = (size_t)b * n + gbase + id0;

    const bool mk0 = cost0 > thr, mk1 = cost1 > thr;
    float2 dv, av;
    dv.x = mk0 ? cost0 : 0.0f;
    dv.y = mk1 ? cost1 : 0.0f;
    av.x = mk0 ? (float)(bpar0 + gbase) : -1.0f;
    av.y = mk1 ? (float)(bpar1 + gbase) : -1.0f;
    *(float2*)(out + go)                 = dv;
    *(float2*)(out + (size_t)B * n + go) = av;

    // ---- Fused per-cloud mean-of-means: last-block-done pattern ----
    if (tid == 0) g_mean_scratch[bp] = mean;
    __threadfence();
    if (tid == 0) s_old = atomicAdd(&g_done_count, 1u);
    __syncthreads();
    if (s_old == (unsigned)(nprim - 1)) {
        __threadfence();
        for (int b2 = tid; b2 < B; b2 += T) {
            float s2 = 0.0f;
            for (int p = 0; p < P; ++p) s2 += g_mean_scratch[b2 * P + p];
            out[(size_t)2 * B * n + b2] = s2 / (float)P;
        }
        if (tid == 0) g_done_count = 0;   // reset for next graph replay
    }
}

extern "C" void kernel_launch(void* const* d_in, const int* in_sizes, int n_in,
                              void* d_out, int out_size)
{
    const float* xyz   = (const float*)d_in[0];
    // d_in[1] = primitive_size (512, compile-time M)
    const float* alpha = (const float*)d_in[2];

    const int Bn = in_sizes[0] / 3;     // B*n
    const int B  = out_size - 2 * Bn;   // out = 2*B*n + B floats
    const int n  = Bn / B;
    const int P  = n / M;
    const int nprim = B * P;

    prim_mst<<<nprim, T>>>(xyz, alpha, (float*)d_out, P, n, B, nprim);
}

// round 9
// speedup vs baseline: 2.9550x; 1.0170x over previous
#include <cuda_runtime.h>
#include <cuda_bf16.h>

#define M 512
#define T 256                 // threads per primitive: 2 nodes per thread
#define NWP (T / 32)          // 8 warps
#define FULL 0xffffffffu
#define EPS_F 1e-12f
#define DEAD 0xffffffffu      // sentinel bits for visited nodes (max uint)

__device__ float    g_mean_scratch[4096];
__device__ unsigned g_done_count = 0;

__global__ void __launch_bounds__(T, 2) prim_mst(
    const float* __restrict__ xyz,
    const float* __restrict__ alpha_p,
    float* __restrict__ out,
    int P, int n, int B, int nprim)
{
    __shared__ float4 sp[M];                                   // node coords (w unused)
    __shared__ alignas(16) unsigned long long s_pack[2][NWP];  // double-buffered warp winners
    __shared__ float s_red[NWP];
    __shared__ unsigned s_old;

    const int tid  = threadIdx.x;
    const int lane = tid & 31;
    const int warp = tid >> 5;
    const int bp   = blockIdx.x;                    // primitive id
    const float* src = xyz + (size_t)bp * (3 * M);

    // Blocked ownership: thread owns nodes id0=2*tid, id1=2*tid+1.
    const int id0 = 2 * tid, id1 = 2 * tid + 1;

    // Coalesced load + publish coords as float4 (single LDS.128 broadcast later).
    {
        const float a0 = __ldg(src + 6 * tid + 0);
        const float a1 = __ldg(src + 6 * tid + 1);
        const float a2 = __ldg(src + 6 * tid + 2);
        const float a3 = __ldg(src + 6 * tid + 3);
        const float a4 = __ldg(src + 6 * tid + 4);
        const float a5 = __ldg(src + 6 * tid + 5);
        sp[id0] = make_float4(a0, a1, a2, 0.0f);
        sp[id1] = make_float4(a3, a4, a5, 0.0f);
    }
    __syncthreads();

    const float4 P0c = sp[id0], P1c = sp[id1];
    const float4 p0  = sp[0];

    // Init: best_d = distance to node 0. Exact reference arithmetic throughout:
    // no FMA contraction (__f*_rn), fmaxf(s, EPS), IEEE __fsqrt_rn, strict <.
    unsigned mv0, mv1;
    {
        float dx = __fsub_rn(P0c.x, p0.x), dy = __fsub_rn(P0c.y, p0.y), dz = __fsub_rn(P0c.z, p0.z);
        float s  = __fadd_rn(__fadd_rn(__fmul_rn(dx, dx), __fmul_rn(dy, dy)), __fmul_rn(dz, dz));
        mv0 = __float_as_uint(__fsqrt_rn(fmaxf(s, EPS_F)));
        dx = __fsub_rn(P1c.x, p0.x); dy = __fsub_rn(P1c.y, p0.y); dz = __fsub_rn(P1c.z, p0.z);
        s  = __fadd_rn(__fadd_rn(__fmul_rn(dx, dx), __fmul_rn(dy, dy)), __fmul_rn(dz, dz));
        mv1 = __float_as_uint(__fsqrt_rn(fmaxf(s, EPS_F)));
    }
    int bpar0 = 0, bpar1 = 0;       // best_p init = 0 (matches reference)
    if (tid == 0) { mv0 = DEAD; bpar0 = -1; }   // node 0 = root, visited

    // One Prim selection step; buf selects the shared double-buffer statically.
    auto step = [&](const int buf) {
        // Local 2-way argmin (strict < : tie -> slot0 == lower node id).
        const bool sel1     = (mv1 < mv0);
        const unsigned lval = sel1 ? mv1 : mv0;
        const unsigned lidx = sel1 ? (unsigned)id1 : (unsigned)id0;

        // Warp argmin: value REDUX, then min node id among value ties (first occurrence).
        const unsigned g    = __reduce_min_sync(FULL, lval);
        const unsigned cand = (lval == g) ? lidx : 0xffffffffu;
        const unsigned wi   = __reduce_min_sync(FULL, cand);
        if (lane == 0)
            s_pack[buf][warp] = ((unsigned long long)g << 32) | wi;
        __syncthreads();

        // Stage 2: all warps redundantly reduce the 8 packed winners via REDUX.
        const unsigned long long pk = s_pack[buf][lane & 7];
        const unsigned v  = (unsigned)(pk >> 32);
        const unsigned ii = (unsigned)pk;
        const unsigned g2 = __reduce_min_sync(FULL, v);
        const unsigned c2 = (v == g2) ? ii : 0xffffffffu;
        const unsigned u  = __reduce_min_sync(FULL, c2);   // min id among value ties

        // Relax both owned nodes against u (exact reference arithmetic).
        const float4 up = sp[u];                     // broadcast LDS.128
        {
            float dx = __fsub_rn(P0c.x, up.x), dy = __fsub_rn(P0c.y, up.y), dz = __fsub_rn(P0c.z, up.z);
            float s  = __fadd_rn(__fadd_rn(__fmul_rn(dx, dx), __fmul_rn(dy, dy)), __fmul_rn(dz, dz));
            const unsigned db = __float_as_uint(__fsqrt_rn(fmaxf(s, EPS_F)));
            const bool isu = ((unsigned)id0 == u);
            const bool upd = (mv0 != DEAD) && !isu && (db < mv0);
            if (upd) { mv0 = db; bpar0 = (int)u; }
            if (isu) { mv0 = DEAD; }
        }
        {
            float dx = __fsub_rn(P1c.x, up.x), dy = __fsub_rn(P1c.y, up.y), dz = __fsub_rn(P1c.z, up.z);
            float s  = __fadd_rn(__fadd_rn(__fmul_rn(dx, dx), __fmul_rn(dy, dy)), __fmul_rn(dz, dz));
            const unsigned db = __float_as_uint(__fsqrt_rn(fmaxf(s, EPS_F)));
            const bool isu = ((unsigned)id1 == u);
            const bool upd = (mv1 != DEAD) && !isu && (db < mv1);
            if (upd) { mv1 = db; bpar1 = (int)u; }
            if (isu) { mv1 = DEAD; }
        }
    };

    // 511 selections = 255 unrolled pairs + 1 tail (buffers alternate 0,1,0,1,...,0).
    for (int itp = 0; itp < (M - 1) / 2; ++itp) {
        step(0);
        step(1);
    }
    step(0);

    // ---- Recompute edge costs from frozen parents (exactly as reference does:
    // pa = max(parent,0); e = pts - pts[pa]; edge = sqrt(max(sum e^2, EPS));
    // cost = where(parent>=0, edge, 0)). Bit-identical to the Prim best_d. ----
    float cost0, cost1;
    {
        const float4 pa = sp[max(bpar0, 0)];
        float dx = __fsub_rn(P0c.x, pa.x), dy = __fsub_rn(P0c.y, pa.y), dz = __fsub_rn(P0c.z, pa.z);
        float s  = __fadd_rn(__fadd_rn(__fmul_rn(dx, dx), __fmul_rn(dy, dy)), __fmul_rn(dz, dz));
        const float e = __fsqrt_rn(fmaxf(s, EPS_F));
        cost0 = (bpar0 >= 0) ? e : 0.0f;
    }
    {
        const float4 pa = sp[max(bpar1, 0)];
        float dx = __fsub_rn(P1c.x, pa.x), dy = __fsub_rn(P1c.y, pa.y), dz = __fsub_rn(P1c.z, pa.z);
        float s  = __fadd_rn(__fadd_rn(__fmul_rn(dx, dx), __fmul_rn(dy, dy)), __fmul_rn(dz, dz));
        const float e = __fsqrt_rn(fmaxf(s, EPS_F));
        cost1 = (bpar1 >= 0) ? e : 0.0f;
    }

    // ---- Mean MST edge length over the primitive ----
    float sum = cost0 + cost1;
    #pragma unroll
    for (int off = 16; off; off >>= 1) sum += __shfl_xor_sync(FULL, sum, off);
    if (lane == 0) s_red[warp] = sum;
    __syncthreads();
    float tot = s_red[0];
    #pragma unroll
    for (int q = 1; q < NWP; ++q) tot += s_red[q];
    const float mean  = tot / (float)(M - 1);
    const float alpha = *alpha_p;
    const float thr   = alpha * mean;

    // ---- Outputs (float2 per array) ----
    const int b     = bp / P;
    const int pl    = bp - b * P;
    const int gbase = pl * M;
    const size_t go = (size_t)b * n + gbase + id0;

    const bool mk0 = cost0 > thr, mk1 = cost1 > thr;
    float2 dv, av;
    dv.x = mk0 ? cost0 : 0.0f;
    dv.y = mk1 ? cost1 : 0.0f;
    av.x = mk0 ? (float)(bpar0 + gbase) : -1.0f;
    av.y = mk1 ? (float)(bpar1 + gbase) : -1.0f;
    *(float2*)(out + go)                 = dv;
    *(float2*)(out + (size_t)B * n + go) = av;

    // ---- Fused per-cloud mean-of-means: last-block-done pattern ----
    if (tid == 0) g_mean_scratch[bp] = mean;
    __threadfence();
    if (tid == 0) s_old = atomicAdd(&g_done_count, 1u);
    __syncthreads();
    if (s_old == (unsigned)(nprim - 1)) {
        __threadfence();
        for (int b2 = tid; b2 < B; b2 += T) {
            float s2 = 0.0f;
            for (int p = 0; p < P; ++p) s2 += g_mean_scratch[b2 * P + p];
            out[(size_t)2 * B * n + b2] = s2 / (float)P;
        }
        if (tid == 0) g_done_count = 0;   // reset for next graph replay
    }
}

extern "C" void kernel_launch(void* const* d_in, const int* in_sizes, int n_in,
                              void* d_out, int out_size)
{
    const float* xyz   = (const float*)d_in[0];
    // d_in[1] = primitive_size (512, compile-time M)
    const float* alpha = (const float*)d_in[2];

    const int Bn = in_sizes[0] / 3;     // B*n
    const int B  = out_size - 2 * Bn;   // out = 2*B*n + B floats
    const int n  = Bn / B;
    const int P  = n / M;
    const int nprim = B * P;

    prim_mst<<<nprim, T>>>(xyz, alpha, (float*)d_out, P, n, B, nprim);
}

// round 10
// speedup vs baseline: 3.2389x; 1.0961x over previous
#include <cuda_runtime.h>
#include <cuda_bf16.h>

#define M 512
#define T 256                 // threads per primitive: 2 nodes per thread
#define NWP (T / 32)          // 8 warps
#define FULL 0xffffffffu
#define EPS_F 1e-12f
#define DEADS 0x80000000u     // visited sentinel: max-loser for unsigned min, INT_MIN for signed cmp

__device__ float    g_mean_scratch[4096];
__device__ unsigned g_done_count = 0;

// ---- packed f32x2 helpers (sm_100+): per-element results are bit-identical
// to the unfused scalar __fsub_rn/__fmul_rn/__fadd_rn sequence. ----
__device__ __forceinline__ unsigned long long pack2(float lo, float hi) {
    unsigned long long r;
    asm("mov.b64 %0, {%1, %2};" : "=l"(r) : "f"(lo), "f"(hi));
    return r;
}
__device__ __forceinline__ void unpack2(unsigned long long v, float& lo, float& hi) {
    asm("mov.b64 {%0, %1}, %2;" : "=f"(lo), "=f"(hi) : "l"(v));
}
__device__ __forceinline__ unsigned long long fma2(unsigned long long a, unsigned long long b,
                                                   unsigned long long c) {
    unsigned long long r;
    asm("fma.rn.f32x2 %0, %1, %2, %3;" : "=l"(r) : "l"(a), "l"(b), "l"(c));
    return r;
}
__device__ __forceinline__ unsigned long long mul2(unsigned long long a, unsigned long long b) {
    unsigned long long r;
    asm("mul.rn.f32x2 %0, %1, %2;" : "=l"(r) : "l"(a), "l"(b));
    return r;
}
__device__ __forceinline__ unsigned long long add2(unsigned long long a, unsigned long long b) {
    unsigned long long r;
    asm("add.rn.f32x2 %0, %1, %2;" : "=l"(r) : "l"(a), "l"(b));
    return r;
}

__global__ void __launch_bounds__(T, 2) prim_mst(
    const float* __restrict__ xyz,
    const float* __restrict__ alpha_p,
    float* __restrict__ out,
    int P, int n, int B, int nprim)
{
    __shared__ float4 sp[M];                                   // node coords (w unused)
    __shared__ alignas(16) unsigned long long s_pack[2][NWP];  // double-buffered warp winners
    __shared__ float s_red[NWP];
    __shared__ unsigned s_old;

    const int tid  = threadIdx.x;
    const int lane = tid & 31;
    const int warp = tid >> 5;
    const int bp   = blockIdx.x;                    // primitive id
    const float* src = xyz + (size_t)bp * (3 * M);

    // Blocked ownership: thread owns nodes id0=2*tid, id1=2*tid+1.
    const int id0 = 2 * tid, id1 = 2 * tid + 1;

    // Coalesced load + publish coords as float4 (single LDS.128 broadcast later).
    {
        const float a0 = __ldg(src + 6 * tid + 0);
        const float a1 = __ldg(src + 6 * tid + 1);
        const float a2 = __ldg(src + 6 * tid + 2);
        const float a3 = __ldg(src + 6 * tid + 3);
        const float a4 = __ldg(src + 6 * tid + 4);
        const float a5 = __ldg(src + 6 * tid + 5);
        sp[id0] = make_float4(a0, a1, a2, 0.0f);
        sp[id1] = make_float4(a3, a4, a5, 0.0f);
    }
    __syncthreads();

    const float4 P0c = sp[id0], P1c = sp[id1];
    // Packed (node0, node1) per component for the f32x2 relax path.
    const unsigned long long pxx = pack2(P0c.x, P1c.x);
    const unsigned long long pyy = pack2(P0c.y, P1c.y);
    const unsigned long long pzz = pack2(P0c.z, P1c.z);
    const unsigned long long NEG1 = 0xBF800000BF800000ULL;   // (-1.0f, -1.0f)

    // Init: best_d = distance to node 0. fma2(u,-1,p) == sub.rn(p,u) bit-exact;
    // then mul/add rn, fmaxf(s,EPS), IEEE __fsqrt_rn — matches reference exactly.
    unsigned mv0, mv1;
    {
        const float4 p0 = sp[0];
        const unsigned long long uxx = pack2(p0.x, p0.x);
        const unsigned long long uyy = pack2(p0.y, p0.y);
        const unsigned long long uzz = pack2(p0.z, p0.z);
        const unsigned long long dx = fma2(uxx, NEG1, pxx);
        const unsigned long long dy = fma2(uyy, NEG1, pyy);
        const unsigned long long dz = fma2(uzz, NEG1, pzz);
        const unsigned long long ss = add2(add2(mul2(dx, dx), mul2(dy, dy)), mul2(dz, dz));
        float s0, s1; unpack2(ss, s0, s1);
        mv0 = __float_as_uint(__fsqrt_rn(fmaxf(s0, EPS_F)));
        mv1 = __float_as_uint(__fsqrt_rn(fmaxf(s1, EPS_F)));
    }
    int bpar0 = 0, bpar1 = 0;       // best_p init = 0 (matches reference)
    if (tid == 0) { mv0 = DEADS; bpar0 = -1; }   // node 0 = root, visited

    // One Prim selection step; buf selects the shared double-buffer statically.
    auto step = [&](const int buf) {
        // Local 2-way argmin, unsigned (DEADS loses; tie -> slot0 == lower node id).
        const bool sel1     = (mv1 < mv0);
        const unsigned lval = sel1 ? mv1 : mv0;
        const unsigned lidx = sel1 ? (unsigned)id1 : (unsigned)id0;

        // Warp argmin: value REDUX.UMIN, then min node id among value ties.
        const unsigned g    = __reduce_min_sync(FULL, lval);
        const unsigned cand = (lval == g) ? lidx : 0xffffffffu;
        const unsigned wi   = __reduce_min_sync(FULL, cand);
        if (lane == 0)
            s_pack[buf][warp] = ((unsigned long long)g << 32) | wi;
        __syncthreads();

        // Stage 2: all warps redundantly reduce the 8 packed winners via REDUX.
        const unsigned long long pk = s_pack[buf][lane & 7];
        const unsigned v  = (unsigned)(pk >> 32);
        const unsigned ii = (unsigned)pk;
        const unsigned g2 = __reduce_min_sync(FULL, v);
        const unsigned c2 = (v == g2) ? ii : 0xffffffffu;
        const unsigned u  = __reduce_min_sync(FULL, c2);   // min id among value ties

        // Relax both owned nodes against u (packed f32x2, bit-exact vs reference).
        const float4 up = sp[u];                     // broadcast LDS.128
        const unsigned long long uxx = pack2(up.x, up.x);
        const unsigned long long uyy = pack2(up.y, up.y);
        const unsigned long long uzz = pack2(up.z, up.z);
        const unsigned long long dx = fma2(uxx, NEG1, pxx);
        const unsigned long long dy = fma2(uyy, NEG1, pyy);
        const unsigned long long dz = fma2(uzz, NEG1, pzz);
        const unsigned long long ss = add2(add2(mul2(dx, dx), mul2(dy, dy)), mul2(dz, dz));
        float s0, s1; unpack2(ss, s0, s1);
        const unsigned db0 = __float_as_uint(__fsqrt_rn(fmaxf(s0, EPS_F)));
        const unsigned db1 = __float_as_uint(__fsqrt_rn(fmaxf(s1, EPS_F)));

        // Owner becomes DEADS before the compare; signed cmp vs INT_MIN is then
        // always false, so no separate alive/!isu predicates are needed.
        mv0 = (u == (unsigned)id0) ? DEADS : mv0;
        mv1 = (u == (unsigned)id1) ? DEADS : mv1;
        if ((int)db0 < (int)mv0) { mv0 = db0; bpar0 = (int)u; }
        if ((int)db1 < (int)mv1) { mv1 = db1; bpar1 = (int)u; }
    };

    // 511 selections = 255 unrolled pairs + 1 tail (buffers alternate 0,1,...,0).
    for (int itp = 0; itp < (M - 1) / 2; ++itp) {
        step(0);
        step(1);
    }
    step(0);

    // ---- Recompute edge costs from frozen parents (exactly as reference:
    // pa = max(parent,0); edge = sqrt(max(sum (p-pa)^2, EPS)); cost = parent>=0 ? edge : 0). ----
    float cost0, cost1;
    {
        const float4 pa = sp[max(bpar0, 0)];
        float dx = __fsub_rn(P0c.x, pa.x), dy = __fsub_rn(P0c.y, pa.y), dz = __fsub_rn(P0c.z, pa.z);
        float s  = __fadd_rn(__fadd_rn(__fmul_rn(dx, dx), __fmul_rn(dy, dy)), __fmul_rn(dz, dz));
        cost0 = (bpar0 >= 0) ? __fsqrt_rn(fmaxf(s, EPS_F)) : 0.0f;
    }
    {
        const float4 pa = sp[max(bpar1, 0)];
        float dx = __fsub_rn(P1c.x, pa.x), dy = __fsub_rn(P1c.y, pa.y), dz = __fsub_rn(P1c.z, pa.z);
        float s  = __fadd_rn(__fadd_rn(__fmul_rn(dx, dx), __fmul_rn(dy, dy)), __fmul_rn(dz, dz));
        cost1 = (bpar1 >= 0) ? __fsqrt_rn(fmaxf(s, EPS_F)) : 0.0f;
    }

    // ---- Mean MST edge length over the primitive ----
    float sum = cost0 + cost1;
    #pragma unroll
    for (int off = 16; off; off >>= 1) sum += __shfl_xor_sync(FULL, sum, off);
    if (lane == 0) s_red[warp] = sum;
    __syncthreads();
    float tot = s_red[0];
    #pragma unroll
    for (int q = 1; q < NWP; ++q) tot += s_red[q];
    const float mean  = tot / (float)(M - 1);
    const float alpha = *alpha_p;
    const float thr   = alpha * mean;

    // ---- Outputs (float2 per array) ----
    const int b     = bp / P;
    const int pl    = bp - b * P;
    const int gbase = pl * M;
    const size_t go = (size_t)b * n + gbase + id0;

    const bool mk0 = cost0 > thr, mk1 = cost1 > thr;
    float2 dv, av;
    dv.x = mk0 ? cost0 : 0.0f;
    dv.y = mk1 ? cost1 : 0.0f;
    av.x = mk0 ? (float)(bpar0 + gbase) : -1.0f;
    av.y = mk1 ? (float)(bpar1 + gbase) : -1.0f;
    *(float2*)(out + go)                 = dv;
    *(float2*)(out + (size_t)B * n + go) = av;

    // ---- Fused per-cloud mean-of-means: last-block-done pattern ----
    if (tid == 0) g_mean_scratch[bp] = mean;
    __threadfence();
    if (tid == 0) s_old = atomicAdd(&g_done_count, 1u);
    __syncthreads();
    if (s_old == (unsigned)(nprim - 1)) {
        __threadfence();
        for (int b2 = tid; b2 < B; b2 += T) {
            float s2 = 0.0f;
            for (int p = 0; p < P; ++p) s2 += g_mean_scratch[b2 * P + p];
            out[(size_t)2 * B * n + b2] = s2 / (float)P;
        }
        if (tid == 0) g_done_count = 0;   // reset for next graph replay
    }
}

extern "C" void kernel_launch(void* const* d_in, const int* in_sizes, int n_in,
                              void* d_out, int out_size)
{
    const float* xyz   = (const float*)d_in[0];
    // d_in[1] = primitive_size (512, compile-time M)
    const float* alpha = (const float*)d_in[2];

    const int Bn = in_sizes[0] / 3;     // B*n
    const int B  = out_size - 2 * Bn;   // out = 2*B*n + B floats
    const int n  = Bn / B;
    const int P  = n / M;
    const int nprim = B * P;

    prim_mst<<<nprim, T>>>(xyz, alpha, (float*)d_out, P, n, B, nprim);
}